// round 2
// baseline (speedup 1.0000x reference)
#include <cuda_runtime.h>
#include <cstdint>

// Problem constants (from reference)
#define NUM_INPUT_NODES  524288
#define NUM_LAYER_NODES  262144
#define BATCH            128
#define NUM_ELS          (NUM_LAYER_NODES + 1)

// One warp per output row. Lane l handles float4 index l of the 128-float row.
// warp 0        -> copy element_mars row 0 (reserved dummy; d_out is poisoned)
// warp w (>=1)  -> out[nids[w-1]] = node_mars[cids[w-1][0]] + node_mars[cids[w-1][1]]
//
// NOTE: JAX silently downcasts int64 -> int32 without x64 mode, so nids/cids
// arrive as int32.
__global__ void __launch_bounds__(256)
prod_layer_kernel(const float* __restrict__ node_mars,
                  const float* __restrict__ element_mars,
                  const int* __restrict__ nids,
                  const int* __restrict__ cids,
                  float* __restrict__ out)
{
    const unsigned gwarp = (blockIdx.x * blockDim.x + threadIdx.x) >> 5;
    const unsigned lane  = threadIdx.x & 31;

    if (gwarp == 0) {
        // Reserved row 0: pass through element_mars[0, :].
        const float4* src = reinterpret_cast<const float4*>(element_mars);
        float4* dst = reinterpret_cast<float4*>(out);
        dst[lane] = src[lane];
        return;
    }

    const unsigned node = gwarp - 1;
    if (node >= NUM_LAYER_NODES) return;

    // int32 indices; all lanes load the same values -> L1 broadcast.
    const long long c0  = (long long)__ldg(&cids[2 * node]);
    const long long c1  = (long long)__ldg(&cids[2 * node + 1]);
    const long long nid = (long long)__ldg(&nids[node]);

    const float4* a = reinterpret_cast<const float4*>(node_mars + c0 * BATCH);
    const float4* b = reinterpret_cast<const float4*>(node_mars + c1 * BATCH);

    float4 va = __ldg(&a[lane]);
    float4 vb = __ldg(&b[lane]);

    float4 r;
    r.x = va.x + vb.x;
    r.y = va.y + vb.y;
    r.z = va.z + vb.z;
    r.w = va.w + vb.w;

    reinterpret_cast<float4*>(out + nid * BATCH)[lane] = r;
}

extern "C" void kernel_launch(void* const* d_in, const int* in_sizes, int n_in,
                              void* d_out, int out_size)
{
    const float* node_mars    = (const float*)d_in[0];
    const float* element_mars = (const float*)d_in[1];
    const int*   nids         = (const int*)d_in[2];
    const int*   cids         = (const int*)d_in[3];
    float*       out          = (float*)d_out;

    // One warp per output row, including the reserved row 0.
    const unsigned total_warps   = NUM_LAYER_NODES + 1;
    const unsigned threads       = 256;                 // 8 warps per block
    const unsigned warps_per_blk = threads / 32;
    const unsigned blocks = (total_warps + warps_per_blk - 1) / warps_per_blk;

    prod_layer_kernel<<<blocks, threads>>>(node_mars, element_mars, nids, cids, out);
}

// round 3
// speedup vs baseline: 1.0877x; 1.0877x over previous
#include <cuda_runtime.h>
#include <cstdint>

#define NUM_INPUT_NODES  524288
#define NUM_LAYER_NODES  262144
#define BATCH            128
#define NODES_PER_WARP   4

// One warp handles 4 consecutive output rows; lane l covers float4 slot l of
// each 128-float row. All 8 gather loads are issued before any store to
// maximize per-warp MLP. Stores use evict-first (.cs) since output is
// write-once, preserving L2 for the duplicate-heavy gather reads.
// The warp whose base == NUM_LAYER_NODES copies reserved row 0.
__global__ void __launch_bounds__(256)
prod_layer_kernel(const float* __restrict__ node_mars,
                  const float* __restrict__ element_mars,
                  const int* __restrict__ nids,
                  const int* __restrict__ cids,
                  float* __restrict__ out)
{
    const unsigned gwarp = (blockIdx.x * blockDim.x + threadIdx.x) >> 5;
    const unsigned lane  = threadIdx.x & 31;
    const unsigned base  = gwarp * NODES_PER_WARP;

    if (base >= NUM_LAYER_NODES) {
        if (base == NUM_LAYER_NODES) {
            // Reserved row 0: pass through element_mars[0, :] (d_out poisoned).
            const float4* src = reinterpret_cast<const float4*>(element_mars);
            float4* dst = reinterpret_cast<float4*>(out);
            dst[lane] = src[lane];
        }
        return;
    }

    // Vector-load indices: 4 nids (int4), 8 cids (2x int4). base % 4 == 0 so
    // both are 16B-aligned. Broadcast across the warp via L1.
    const int4 n4  = __ldg(reinterpret_cast<const int4*>(&nids[base]));
    const int4 c01 = __ldg(reinterpret_cast<const int4*>(&cids[2 * base]));
    const int4 c23 = __ldg(reinterpret_cast<const int4*>(&cids[2 * base + 4]));

    const float4* nm = reinterpret_cast<const float4*>(node_mars);
    const unsigned F4 = BATCH / 4;   // 32 float4 per row

    // Issue all 8 gather loads up front (independent -> 8 outstanding).
    float4 a0 = __ldg(&nm[(long long)c01.x * F4 + lane]);
    float4 b0 = __ldg(&nm[(long long)c01.y * F4 + lane]);
    float4 a1 = __ldg(&nm[(long long)c01.z * F4 + lane]);
    float4 b1 = __ldg(&nm[(long long)c01.w * F4 + lane]);
    float4 a2 = __ldg(&nm[(long long)c23.x * F4 + lane]);
    float4 b2 = __ldg(&nm[(long long)c23.y * F4 + lane]);
    float4 a3 = __ldg(&nm[(long long)c23.z * F4 + lane]);
    float4 b3 = __ldg(&nm[(long long)c23.w * F4 + lane]);

    float4* o = reinterpret_cast<float4*>(out);

    float4 r0 = make_float4(a0.x + b0.x, a0.y + b0.y, a0.z + b0.z, a0.w + b0.w);
    __stcs(&o[(long long)n4.x * F4 + lane], r0);
    float4 r1 = make_float4(a1.x + b1.x, a1.y + b1.y, a1.z + b1.z, a1.w + b1.w);
    __stcs(&o[(long long)n4.y * F4 + lane], r1);
    float4 r2 = make_float4(a2.x + b2.x, a2.y + b2.y, a2.z + b2.z, a2.w + b2.w);
    __stcs(&o[(long long)n4.z * F4 + lane], r2);
    float4 r3 = make_float4(a3.x + b3.x, a3.y + b3.y, a3.z + b3.z, a3.w + b3.w);
    __stcs(&o[(long long)n4.w * F4 + lane], r3);
}

extern "C" void kernel_launch(void* const* d_in, const int* in_sizes, int n_in,
                              void* d_out, int out_size)
{
    const float* node_mars    = (const float*)d_in[0];
    const float* element_mars = (const float*)d_in[1];
    const int*   nids         = (const int*)d_in[2];
    const int*   cids         = (const int*)d_in[3];
    float*       out          = (float*)d_out;

    // 262144/4 = 65536 work warps + 1 warp for reserved row 0.
    const unsigned total_warps   = NUM_LAYER_NODES / NODES_PER_WARP + 1;
    const unsigned threads       = 256;               // 8 warps/block
    const unsigned warps_per_blk = threads / 32;
    const unsigned blocks = (total_warps + warps_per_blk - 1) / warps_per_blk;

    prod_layer_kernel<<<blocks, threads>>>(node_mars, element_mars, nids, cids, out);
}

// round 4
// speedup vs baseline: 1.0913x; 1.0033x over previous
#include <cuda_runtime.h>
#include <cstdint>

#define NUM_INPUT_NODES  524288
#define NUM_LAYER_NODES  262144
#define BATCH            128
#define NODES_PER_WARP   8

// One warp handles 8 consecutive output rows; lane l covers float4 slot l of
// each 128-float row. All 16 gather loads are issued before any add/store to
// maximize per-warp memory-level parallelism (8KB outstanding per warp).
// Stores use evict-first (.cs): output is write-once and must not evict the
// duplicate-heavy gather rows from L2.
// The warp whose base == NUM_LAYER_NODES copies reserved row 0.
__global__ void __launch_bounds__(256)
prod_layer_kernel(const float* __restrict__ node_mars,
                  const float* __restrict__ element_mars,
                  const int* __restrict__ nids,
                  const int* __restrict__ cids,
                  float* __restrict__ out)
{
    const unsigned gwarp = (blockIdx.x * blockDim.x + threadIdx.x) >> 5;
    const unsigned lane  = threadIdx.x & 31;
    const unsigned base  = gwarp * NODES_PER_WARP;

    if (base >= NUM_LAYER_NODES) {
        if (base == NUM_LAYER_NODES) {
            // Reserved row 0: pass through element_mars[0, :] (d_out poisoned).
            const float4* src = reinterpret_cast<const float4*>(element_mars);
            float4* dst = reinterpret_cast<float4*>(out);
            dst[lane] = src[lane];
        }
        return;
    }

    // Vector-load indices: 8 nids (2x int4), 16 cids (4x int4); 16B-aligned.
    const int4 n03  = __ldg(reinterpret_cast<const int4*>(&nids[base]));
    const int4 n47  = __ldg(reinterpret_cast<const int4*>(&nids[base + 4]));
    const int4 cA   = __ldg(reinterpret_cast<const int4*>(&cids[2 * base]));
    const int4 cB   = __ldg(reinterpret_cast<const int4*>(&cids[2 * base + 4]));
    const int4 cC   = __ldg(reinterpret_cast<const int4*>(&cids[2 * base + 8]));
    const int4 cD   = __ldg(reinterpret_cast<const int4*>(&cids[2 * base + 12]));

    const float4* nm = reinterpret_cast<const float4*>(node_mars);
    const unsigned F4 = BATCH / 4;   // 32 float4 per row

    // Issue all 16 gather loads up front (independent -> 16 outstanding).
    float4 a0 = __ldg(&nm[(long long)cA.x * F4 + lane]);
    float4 b0 = __ldg(&nm[(long long)cA.y * F4 + lane]);
    float4 a1 = __ldg(&nm[(long long)cA.z * F4 + lane]);
    float4 b1 = __ldg(&nm[(long long)cA.w * F4 + lane]);
    float4 a2 = __ldg(&nm[(long long)cB.x * F4 + lane]);
    float4 b2 = __ldg(&nm[(long long)cB.y * F4 + lane]);
    float4 a3 = __ldg(&nm[(long long)cB.z * F4 + lane]);
    float4 b3 = __ldg(&nm[(long long)cB.w * F4 + lane]);
    float4 a4 = __ldg(&nm[(long long)cC.x * F4 + lane]);
    float4 b4 = __ldg(&nm[(long long)cC.y * F4 + lane]);
    float4 a5 = __ldg(&nm[(long long)cC.z * F4 + lane]);
    float4 b5 = __ldg(&nm[(long long)cC.w * F4 + lane]);
    float4 a6 = __ldg(&nm[(long long)cD.x * F4 + lane]);
    float4 b6 = __ldg(&nm[(long long)cD.y * F4 + lane]);
    float4 a7 = __ldg(&nm[(long long)cD.z * F4 + lane]);
    float4 b7 = __ldg(&nm[(long long)cD.w * F4 + lane]);

    float4* o = reinterpret_cast<float4*>(out);

    float4 r;
    r = make_float4(a0.x + b0.x, a0.y + b0.y, a0.z + b0.z, a0.w + b0.w);
    __stcs(&o[(long long)n03.x * F4 + lane], r);
    r = make_float4(a1.x + b1.x, a1.y + b1.y, a1.z + b1.z, a1.w + b1.w);
    __stcs(&o[(long long)n03.y * F4 + lane], r);
    r = make_float4(a2.x + b2.x, a2.y + b2.y, a2.z + b2.z, a2.w + b2.w);
    __stcs(&o[(long long)n03.z * F4 + lane], r);
    r = make_float4(a3.x + b3.x, a3.y + b3.y, a3.z + b3.z, a3.w + b3.w);
    __stcs(&o[(long long)n03.w * F4 + lane], r);
    r = make_float4(a4.x + b4.x, a4.y + b4.y, a4.z + b4.z, a4.w + b4.w);
    __stcs(&o[(long long)n47.x * F4 + lane], r);
    r = make_float4(a5.x + b5.x, a5.y + b5.y, a5.z + b5.z, a5.w + b5.w);
    __stcs(&o[(long long)n47.y * F4 + lane], r);
    r = make_float4(a6.x + b6.x, a6.y + b6.y, a6.z + b6.z, a6.w + b6.w);
    __stcs(&o[(long long)n47.z * F4 + lane], r);
    r = make_float4(a7.x + b7.x, a7.y + b7.y, a7.z + b7.z, a7.w + b7.w);
    __stcs(&o[(long long)n47.w * F4 + lane], r);
}

extern "C" void kernel_launch(void* const* d_in, const int* in_sizes, int n_in,
                              void* d_out, int out_size)
{
    const float* node_mars    = (const float*)d_in[0];
    const float* element_mars = (const float*)d_in[1];
    const int*   nids         = (const int*)d_in[2];
    const int*   cids         = (const int*)d_in[3];
    float*       out          = (float*)d_out;

    // 262144/8 = 32768 work warps + 1 warp for reserved row 0.
    const unsigned total_warps   = NUM_LAYER_NODES / NODES_PER_WARP + 1;
    const unsigned threads       = 256;               // 8 warps/block
    const unsigned warps_per_blk = threads / 32;
    const unsigned blocks = (total_warps + warps_per_blk - 1) / warps_per_blk;

    prod_layer_kernel<<<blocks, threads>>>(node_mars, element_mars, nids, cids, out);
}